// round 1
// baseline (speedup 1.0000x reference)
#include <cuda_runtime.h>
#include <cstdint>

#define ROWS_PER_BLOCK 512
#define BLOCK_THREADS  256
#define D_IN           1024
#define NCHUNK         32      // 1024 / 32 k per chunk
#define CHUNK_K        32

// ---------- packed f32x2 helpers ----------
__device__ __forceinline__ unsigned long long pack2(float v) {
    unsigned long long r;
    asm("mov.b64 %0, {%1, %1};" : "=l"(r) : "f"(v));
    return r;
}
__device__ __forceinline__ unsigned long long fma2(unsigned long long a,
                                                   unsigned long long b,
                                                   unsigned long long c) {
    unsigned long long d;
    asm("fma.rn.f32x2 %0, %1, %2, %3;" : "=l"(d) : "l"(a), "l"(b), "l"(c));
    return d;
}
__device__ __forceinline__ float2 unpack2(unsigned long long v) {
    float2 f;
    asm("mov.b64 {%0, %1}, %2;" : "=f"(f.x), "=f"(f.y) : "l"(v));
    return f;
}

// ---------- cp.async 16B ----------
__device__ __forceinline__ void cp16(uint32_t smem_dst, const void* gsrc) {
    asm volatile("cp.async.cg.shared.global [%0], [%1], 16;\n"
                 :: "r"(smem_dst), "l"(gsrc));
}
__device__ __forceinline__ void cp_commit() {
    asm volatile("cp.async.commit_group;\n");
}

// ---------- epilogue math ----------
__device__ __forceinline__ float softplus_f(float v) {
    // matches jax.nn.softplus: max(v,0) + log1p(exp(-|v|))
    return fmaxf(v, 0.0f) + log1pf(expf(-fabsf(v)));
}

__device__ __forceinline__ void rodrigues(float x, float y, float z, float* R) {
    float n2 = x * x + y * y + z * z;
    float th = sqrtf(n2);
    float inv = 1.0f / th;               // same singularity behavior as reference
    float ax = x * inv, ay = y * inv, az = z * inv;
    float st, ct;
    sincosf(th, &st, &ct);
    float oc = 1.0f - ct;
    R[0] = ct + oc * ax * ax; R[1] = oc * ax * ay - st * az; R[2] = oc * ax * az + st * ay;
    R[3] = oc * ax * ay + st * az; R[4] = ct + oc * ay * ay; R[5] = oc * ay * az - st * ax;
    R[6] = oc * ax * az - st * ay; R[7] = oc * ay * az + st * ax; R[8] = ct + oc * az * az;
}

__device__ __forceinline__ void finalize_row(
    int row,
    float s0, float s1, float s2, float s3, float s4,
    float s5, float s6, float s7, float s8,
    const float* __restrict__ eps,
    const float* __restrict__ bmu, const float* __restrict__ bd,
    const float* __restrict__ bl, float* __restrict__ out)
{
    float mu0 = s0 + bmu[0], mu1 = s1 + bmu[1], mu2 = s2 + bmu[2];
    float d0 = softplus_f(s3 + bd[0]);
    float d1 = softplus_f(s4 + bd[1]);
    float d2 = softplus_f(s5 + bd[2]);
    float l0 = s6 + bl[0], l1 = s7 + bl[1], l2 = s8 + bl[2];

    const float* e = eps + (size_t)row * 3;
    float t0 = sqrtf(d0) * e[0];
    float t1 = sqrtf(d1) * e[1];
    float t2 = sqrtf(d2) * e[2];

    // v = L @ t, L = [[1,0,0],[l0,1,0],[l1,l2,1]]
    float v0 = t0;
    float v1 = l0 * t0 + t1;
    float v2 = l1 * t0 + l2 * t1 + t2;

    float Rm[9], Rv[9];
    rodrigues(mu0, mu1, mu2, Rm);
    rodrigues(v0, v1, v2, Rv);

    float* o = out + (size_t)row * 9;
#pragma unroll
    for (int i = 0; i < 3; ++i) {
#pragma unroll
        for (int j = 0; j < 3; ++j) {
            o[i * 3 + j] = Rm[i * 3 + 0] * Rv[0 + j]
                         + Rm[i * 3 + 1] * Rv[3 + j]
                         + Rm[i * 3 + 2] * Rv[6 + j];
        }
    }
}

union F4U { float4 v; float f[4]; };

// Dynamic smem layout:
//   float wsm[1024*12]                       (48 KB, weights padded to 12/k)
//   float xt[2][ROWS_PER_BLOCK * CHUNK_K]    (2 x 64 KB, double-buffered x tile)
#define WSM_FLOATS (D_IN * 12)
#define XT_FLOATS  (ROWS_PER_BLOCK * CHUNK_K)
#define SMEM_BYTES ((WSM_FLOATS + 2 * XT_FLOATS) * 4)

__global__ __launch_bounds__(BLOCK_THREADS, 1)
void so3_fused_kernel(const float* __restrict__ x,
                      const float* __restrict__ eps,
                      const float* __restrict__ Wmu, const float* __restrict__ bmu,
                      const float* __restrict__ Wd,  const float* __restrict__ bd,
                      const float* __restrict__ Wl,  const float* __restrict__ bl,
                      float* __restrict__ out)
{
    extern __shared__ float smem[];
    float* wsm = smem;                 // weights
    float* xt  = smem + WSM_FLOATS;    // x tiles (2 buffers)

    const int tid = threadIdx.x;
    const int rowbase = blockIdx.x * ROWS_PER_BLOCK;

    // ---- stage packed weights into smem (every block; W is hot in L2) ----
    for (int k = tid; k < D_IN; k += BLOCK_THREADS) {
        float* o = wsm + k * 12;
        o[0] = Wmu[3 * k + 0]; o[1] = Wmu[3 * k + 1]; o[2] = Wmu[3 * k + 2];
        o[3] = Wd [3 * k + 0]; o[4] = Wd [3 * k + 1]; o[5] = Wd [3 * k + 2];
        o[6] = Wl [3 * k + 0]; o[7] = Wl [3 * k + 1]; o[8] = Wl [3 * k + 2];
        o[9] = 0.0f; o[10] = 0.0f; o[11] = 0.0f;
    }

    const uint32_t xts = (uint32_t)__cvta_generic_to_shared(xt);

    // x-tile loader: 512 rows x 32 k, 16B-chunk XOR swizzle (c ^ (row&7))
    auto load_chunk = [&](int chunk, int buf) {
        const float* gx = x + (size_t)rowbase * D_IN + (size_t)chunk * CHUNK_K;
        uint32_t dbase = xts + (uint32_t)buf * (XT_FLOATS * 4);
#pragma unroll
        for (int it = 0; it < 16; ++it) {
            int idx = tid + it * BLOCK_THREADS;   // 0..4095
            int row = idx >> 3;
            int c   = idx & 7;
            uint32_t d = dbase + (uint32_t)(row * 128 + (((c ^ (row & 7))) << 4));
            cp16(d, gx + (size_t)row * D_IN + c * 4);
        }
        cp_commit();
    };

    load_chunk(0, 0);
    load_chunk(1, 1);

    const int warp = tid >> 5;
    const int lane = tid & 31;
    const int rA = warp * 64 + lane;   // local row A
    const int rB = rA + 32;            // local row B (same swizzle phase: 32 % 8 == 0)
    const int q  = rA & 7;

    unsigned long long a0 = 0, a1 = 0, a2 = 0, a3 = 0, a4 = 0;
    unsigned long long b0 = 0, b1 = 0, b2 = 0, b3 = 0, b4 = 0;

    for (int chunk = 0; chunk < NCHUNK; ++chunk) {
        asm volatile("cp.async.wait_group 1;\n");
        __syncthreads();

        const int buf = chunk & 1;
        const float* xa_row = xt + buf * XT_FLOATS + rA * CHUNK_K;
        const float* xb_row = xt + buf * XT_FLOATS + rB * CHUNK_K;
        const float* wp = wsm + chunk * (CHUNK_K * 12);

#pragma unroll
        for (int c = 0; c < 8; ++c) {
            F4U xa4, xb4;
            xa4.v = *(const float4*)(xa_row + ((c ^ q) << 2));
            xb4.v = *(const float4*)(xb_row + ((c ^ q) << 2));
            const float* wf = wp + c * 48;
#pragma unroll
            for (int kk = 0; kk < 4; ++kk) {
                ulonglong2 wA = *(const ulonglong2*)(wf + kk * 12);      // (w0,w1),(w2,w3)
                ulonglong2 wB = *(const ulonglong2*)(wf + kk * 12 + 4);  // (w4,w5),(w6,w7)
                unsigned long long w8 = *(const unsigned long long*)(wf + kk * 12 + 8); // (w8,0)
                unsigned long long xad = pack2(xa4.f[kk]);
                unsigned long long xbd = pack2(xb4.f[kk]);
                a0 = fma2(xad, wA.x, a0);
                a1 = fma2(xad, wA.y, a1);
                a2 = fma2(xad, wB.x, a2);
                a3 = fma2(xad, wB.y, a3);
                a4 = fma2(xad, w8,   a4);
                b0 = fma2(xbd, wA.x, b0);
                b1 = fma2(xbd, wA.y, b1);
                b2 = fma2(xbd, wB.x, b2);
                b3 = fma2(xbd, wB.y, b3);
                b4 = fma2(xbd, w8,   b4);
            }
        }

        __syncthreads();
        if (chunk + 2 < NCHUNK) {
            load_chunk(chunk + 2, buf);
        } else {
            cp_commit();   // empty group keeps wait_group accounting correct
        }
    }

    // ---- epilogue: two rows per thread ----
    {
        float2 p0 = unpack2(a0), p1 = unpack2(a1), p2 = unpack2(a2),
               p3 = unpack2(a3), p4 = unpack2(a4);
        finalize_row(rowbase + rA,
                     p0.x, p0.y, p1.x,   // mu raw
                     p1.y, p2.x, p2.y,   // d raw
                     p3.x, p3.y, p4.x,   // l raw
                     eps, bmu, bd, bl, out);
    }
    {
        float2 p0 = unpack2(b0), p1 = unpack2(b1), p2 = unpack2(b2),
               p3 = unpack2(b3), p4 = unpack2(b4);
        finalize_row(rowbase + rB,
                     p0.x, p0.y, p1.x,
                     p1.y, p2.x, p2.y,
                     p3.x, p3.y, p4.x,
                     eps, bmu, bd, bl, out);
    }
}

extern "C" void kernel_launch(void* const* d_in, const int* in_sizes, int n_in,
                              void* d_out, int out_size)
{
    const float* x   = (const float*)d_in[0];
    const float* eps = (const float*)d_in[1];
    const float* Wmu = (const float*)d_in[2];
    const float* bmu = (const float*)d_in[3];
    const float* Wd  = (const float*)d_in[4];
    const float* bd  = (const float*)d_in[5];
    const float* Wl  = (const float*)d_in[6];
    const float* bl  = (const float*)d_in[7];
    float* out = (float*)d_out;

    cudaFuncSetAttribute(so3_fused_kernel,
                         cudaFuncAttributeMaxDynamicSharedMemorySize, SMEM_BYTES);

    const int nblocks = 65536 / ROWS_PER_BLOCK;   // 128
    so3_fused_kernel<<<nblocks, BLOCK_THREADS, SMEM_BYTES>>>(
        x, eps, Wmu, bmu, Wd, bd, Wl, bl, out);
}